// round 10
// baseline (speedup 1.0000x reference)
#include <cuda_runtime.h>
#include <stdint.h>
#include <math.h>

#define BB   2
#define NN_  16384
#define NP   2048
#define NS   32
#define CIN  64
#define CD   256
#define NP8  256
#define FPS_CL 4          // cluster size (CTAs per batch)
#define PPC  (NN_/FPS_CL) // points per CTA = 4096

// ---- scratch (device globals; allocation is forbidden) ----
__device__ int   g_nn[BB*NP*NS];
__device__ int   g_cnt[BB*NP];
__device__ float g_x   [BB*CD*NP];
__device__ float g_q   [BB*NP8*CD];
__device__ float g_k   [BB*NP8*CD];
__device__ float g_sim [BB*CD*CD];
__device__ float g_affE[BB*CD*CD];
__device__ float g_s   [BB*CD];
__device__ float g_e   [BB*CD];
__device__ float g_part[2*BB*4*NP8*CD];
__device__ int   g_prog[BB];
__device__ int   g_ready[BB*NP];

__device__ __forceinline__ unsigned f2ord(float f){
    unsigned u=__float_as_uint(f);
    return (u&0x80000000u)? ~u : (u|0x80000000u);
}
__device__ __forceinline__ float ord2f(unsigned v){
    unsigned u=(v&0x80000000u)? (v&0x7fffffffu) : ~v;
    return __uint_as_float(u);
}
__device__ __forceinline__ int spread3(int b){
    return (b&1) | ((b&2)<<2) | ((b&4)<<4);
}
__device__ __forceinline__ unsigned int smem_u32(const void* p){
    unsigned int a;
    asm("{.reg .u64 t; cvta.to.shared.u64 t, %1; cvt.u32.u64 %0, t;}" : "=r"(a) : "l"(p));
    return a;
}
__device__ __forceinline__ void st_cluster_u64(unsigned int laddr, unsigned rank, unsigned long long v){
    unsigned int ra;
    asm volatile("mapa.shared::cluster.u32 %0, %1, %2;" : "=r"(ra) : "r"(laddr), "r"(rank));
    asm volatile("st.shared::cluster.u64 [%0], %1;" :: "r"(ra), "l"(v) : "memory");
}

// =============== 0) init: reset progress/ready flags ===============
__global__ void init_kernel()
{
    int t = blockIdx.x*blockDim.x + threadIdx.x;
    if (t < BB) g_prog[t] = 0;
    for (int i = t; i < BB*NP; i += gridDim.x*blockDim.x) g_ready[i] = 0;
}

// =====================================================================
// 1) FPS: cluster of 4 CTAs per batch, 4096 pts/CTA (8/thread), Morton
//    sort, u64 keys, DSMEM cross-CTA exchange, 1 CTA-bar + 1 cluster-bar
//    per iteration. Progress published for overlapped consumers.
// =====================================================================
__global__ __launch_bounds__(512) __cluster_dims__(FPS_CL,1,1)
void fps_kernel(const float* __restrict__ xyz, float* __restrict__ d_out)
{
    extern __shared__ char smraw[];
    float2* sxy = (float2*)smraw;                          // 4096 float2
    float*  szz = (float*)(sxy + PPC);                     // 4096
    unsigned short* sid = (unsigned short*)(szz + PPC);    // 4096
    int* hist = (int*)(sid + PPC);                         // 512
    unsigned long long* xslot = (unsigned long long*)(hist + 512); // [2][4][3]
    unsigned* wvs = (unsigned*)(xslot + 24);               // [2][16]
    unsigned* wls = wvs + 32;                              // [2][16]
    int* wsum = (int*)(wls + 32);                          // 16
    unsigned* bmin = (unsigned*)(wsum + 16);               // 3
    unsigned* bmax = bmin + 3;                             // 3

    const int cb = blockIdx.x;
    const int b  = cb >> 2;                 // batch
    unsigned rank;
    asm("mov.u32 %0, %%cluster_ctarank;" : "=r"(rank));
    const int t = threadIdx.x, lane = t & 31, w = t >> 5;
    const float* X = xyz + (size_t)b*NN_*3;
    const unsigned int xbase = smem_u32(xslot);

    if (t < 512) hist[t] = 0;
    if (t < 3) { bmin[t] = 0xFFFFFFFFu; bmax[t] = 0u; }
    __syncthreads();

    // ---- pass A: global bbox (each CTA reads all points; identical result) ----
    {
        float lx=3.4e38f, ly=3.4e38f, lz=3.4e38f, hx=-3.4e38f, hy=-3.4e38f, hz=-3.4e38f;
#pragma unroll
        for (int j=0;j<32;j++){
            int p=j*512+t;
            float x=X[3*p], y=X[3*p+1], z=X[3*p+2];
            lx=fminf(lx,x); hx=fmaxf(hx,x);
            ly=fminf(ly,y); hy=fmaxf(hy,y);
            lz=fminf(lz,z); hz=fmaxf(hz,z);
        }
        atomicMin(&bmin[0], f2ord(lx)); atomicMax(&bmax[0], f2ord(hx));
        atomicMin(&bmin[1], f2ord(ly)); atomicMax(&bmax[1], f2ord(hy));
        atomicMin(&bmin[2], f2ord(lz)); atomicMax(&bmax[2], f2ord(hz));
    }
    __syncthreads();
    float LX=ord2f(bmin[0]), LY=ord2f(bmin[1]), LZ=ord2f(bmin[2]);
    float invx=8.f/fmaxf(ord2f(bmax[0])-LX,1e-12f);
    float invy=8.f/fmaxf(ord2f(bmax[1])-LY,1e-12f);
    float invz=8.f/fmaxf(ord2f(bmax[2])-LZ,1e-12f);

    // ---- pass B: Morton histogram over OWN slice ----
#pragma unroll
    for (int j=0;j<PPC/512;j++){
        int p=rank*PPC + j*512 + t;
        float x=X[3*p], y=X[3*p+1], z=X[3*p+2];
        int bx=min(7,(int)((x-LX)*invx));
        int by=min(7,(int)((y-LY)*invy));
        int bz=min(7,(int)((z-LZ)*invz));
        atomicAdd(&hist[(spread3(bx)<<2)|(spread3(by)<<1)|spread3(bz)],1);
    }
    __syncthreads();

    // ---- exclusive scan hist[512] ----
    int cnt=hist[t], v=cnt;
#pragma unroll
    for (int d=1; d<32; d<<=1){ int o=__shfl_up_sync(0xffffffffu, v, d); if (lane>=d) v+=o; }
    if (lane==31) wsum[w]=v;
    __syncthreads();
    if (t<16){
        int s=wsum[t];
#pragma unroll
        for (int d=1; d<16; d<<=1){ int o=__shfl_up_sync(0x0000ffffu, s, d); if (t>=d) s+=o; }
        wsum[t]=s;
    }
    __syncthreads();
    { int add=(w>0)? wsum[w-1]:0; hist[t]=v+add-cnt; }
    __syncthreads();

    // ---- pass C: scatter own slice; A(pos)=((pos&7)<<9)|(pos>>3) ----
#pragma unroll
    for (int j=0;j<PPC/512;j++){
        int p=rank*PPC + j*512 + t;
        float x=X[3*p], y=X[3*p+1], z=X[3*p+2];
        int bx=min(7,(int)((x-LX)*invx));
        int by=min(7,(int)((y-LY)*invy));
        int bz=min(7,(int)((z-LZ)*invz));
        int pos=atomicAdd(&hist[(spread3(bx)<<2)|(spread3(by)<<1)|spread3(bz)],1);
        int A=((pos&7)<<9)|(pos>>3);
        sxy[A]=make_float2(x,y); szz[A]=z; sid[A]=(unsigned short)p;
    }
    __syncthreads();

    // ---- per-thread (8 pts) bbox, warp bbox, mind ----
    float mind[8];
    float tlx=3.4e38f, tly=3.4e38f, tlz=3.4e38f, thx=-3.4e38f, thy=-3.4e38f, thz=-3.4e38f;
#pragma unroll
    for (int j=0;j<8;j++){
        int A=(j<<9)|t;
        float2 xy=sxy[A]; float zz=szz[A];
        tlx=fminf(tlx,xy.x); thx=fmaxf(thx,xy.x);
        tly=fminf(tly,xy.y); thy=fmaxf(thy,xy.y);
        tlz=fminf(tlz,zz);   thz=fmaxf(thz,zz);
        mind[j]=3.4e38f;
    }
    float wlx=tlx, wly=tly, wlz=tlz, whx=thx, why_=thy, whz=thz;
#pragma unroll
    for (int off=16; off>0; off>>=1){
        wlx=fminf(wlx,__shfl_xor_sync(0xffffffffu,wlx,off));
        wly=fminf(wly,__shfl_xor_sync(0xffffffffu,wly,off));
        wlz=fminf(wlz,__shfl_xor_sync(0xffffffffu,wlz,off));
        whx=fmaxf(whx,__shfl_xor_sync(0xffffffffu,whx,off));
        why_=fmaxf(why_,__shfl_xor_sync(0xffffffffu,why_,off));
        whz=fmaxf(whz,__shfl_xor_sync(0xffffffffu,whz,off));
    }

    unsigned long long tkey=0ull; float tval=3.4e38f;
    unsigned wmx=0u, wlo=0u; float wval=3.4e38f;

    float nx=X[0], ny=X[1], nz=X[2];
    if (rank==0 && t==0){
        d_out[(size_t)b*NP*3]=nx; d_out[(size_t)b*NP*3+1]=ny; d_out[(size_t)b*NP*3+2]=nz;
    }

    for (int it=1; it<NP; it++){
        int buf=it&1;
        float wdx=fmaxf(fmaxf(wlx-nx, nx-whx),0.f);
        float wdy=fmaxf(fmaxf(wly-ny, ny-why_),0.f);
        float wdz=fmaxf(fmaxf(wlz-nz, nz-whz),0.f);
        float wdd=wdx*wdx+wdy*wdy+wdz*wdz;
        if (wdd*0.99f < wval){
            float ddx=fmaxf(fmaxf(tlx-nx, nx-thx),0.f);
            float ddy=fmaxf(fmaxf(tly-ny, ny-thy),0.f);
            float ddz=fmaxf(fmaxf(tlz-nz, nz-thz),0.f);
            float dd=ddx*ddx+ddy*ddy+ddz*ddz;
            if (dd*0.99f < tval){
                unsigned long long bk=0ull;
#pragma unroll
                for (int j=0;j<8;j++){
                    int A=(j<<9)|t;
                    float2 xy=sxy[A]; float zz=szz[A];
                    float dx=__fsub_rn(xy.x,nx), dy=__fsub_rn(xy.y,ny), dz=__fsub_rn(zz,nz);
                    float d=__fadd_rn(__fadd_rn(__fmul_rn(dx,dx),__fmul_rn(dy,dy)),__fmul_rn(dz,dz));
                    float m=fminf(mind[j],d); mind[j]=m;
                    unsigned long long key=((unsigned long long)__float_as_uint(m)<<32)
                        | (unsigned)((((unsigned)sid[A])^0xFFFFu)<<16) | (unsigned)A;
                    bk = (bk>key)? bk : key;
                }
                tkey=bk; tval=__uint_as_float((unsigned)(bk>>32));
            }
            unsigned uv=(unsigned)(tkey>>32);
            unsigned mx=__reduce_max_sync(0xffffffffu, uv);
            unsigned lo=(uv==mx)? (unsigned)tkey : 0u;
            unsigned mlo=__reduce_max_sync(0xffffffffu, lo);
            wmx=mx; wlo=mlo; wval=__uint_as_float(mx);
        }
        if (lane==0){ wvs[buf*16+w]=wmx; wls[buf*16+w]=wlo; }
        __syncthreads();
        if (w==0){
            unsigned uv2=wvs[buf*16+(lane&15)], lo2=wls[buf*16+(lane&15)];
            unsigned m2=__reduce_max_sync(0xffffffffu, uv2);
            unsigned c2=(uv2==m2)? lo2 : 0u;
            unsigned l2=__reduce_max_sync(0xffffffffu, c2);
            int A=(int)(l2 & 0xFFFFu);
            float2 cxy=sxy[A]; float cz=szz[A];
            unsigned long long key=((unsigned long long)m2<<32)|l2;
            unsigned long long xy=((unsigned long long)__float_as_uint(cxy.y)<<32)|(unsigned)__float_as_uint(cxy.x);
            unsigned long long zw=(unsigned long long)__float_as_uint(cz);
            if (lane<FPS_CL){
                unsigned int base=xbase + (unsigned)(buf*4+rank)*24u;
                st_cluster_u64(base,     (unsigned)lane, key);
                st_cluster_u64(base+8u,  (unsigned)lane, xy);
                st_cluster_u64(base+16u, (unsigned)lane, zw);
            }
        }
        asm volatile("barrier.cluster.arrive.aligned;" ::: "memory");
        asm volatile("barrier.cluster.wait.aligned;"   ::: "memory");
        // pick global winner among the 4 CTA candidates (deterministic)
        const unsigned long long* sl = xslot + buf*12;
        unsigned long long kb=sl[0]; int rb=0;
#pragma unroll
        for (int r=1;r<FPS_CL;r++){ unsigned long long kr=sl[r*3]; if (kr>kb){kb=kr; rb=r;} }
        unsigned long long xyv=sl[rb*3+1], zv=sl[rb*3+2];
        nx=__uint_as_float((unsigned)xyv);
        ny=__uint_as_float((unsigned)(xyv>>32));
        nz=__uint_as_float((unsigned)zv);
        if (rank==0 && t==0){
            d_out[((size_t)b*NP+it)*3  ]=nx;
            d_out[((size_t)b*NP+it)*3+1]=ny;
            d_out[((size_t)b*NP+it)*3+2]=nz;
            if ((it&7)==7 || it==NP-1){
                __threadfence();
                *(volatile int*)&g_prog[b] = it+1;
            }
        }
    }
}

// =============== 2) ball query (warp per center, progressive) ===============
__global__ __launch_bounds__(128) void ballquery_kernel(const float* __restrict__ xyz,
                                                        const float* __restrict__ centers)
{
    int gw = (blockIdx.x*blockDim.x + threadIdx.x)>>5;
    int lane = threadIdx.x & 31;
    if (gw >= BB*NP) return;
    int b = gw / NP, c = gw % NP;
    {
        volatile int* pr = &g_prog[b];
        while (*pr <= c) __nanosleep(128);
        __threadfence();
    }
    const float* X = xyz + (size_t)b*NN_*3;
    float cx=centers[gw*3], cy=centers[gw*3+1], cz=centers[gw*3+2];
    __shared__ int lists[4][NS];
    int* list = lists[threadIdx.x>>5];
    int found=0;
    for (int base=0; base<NN_; base+=32){
        int p=base+lane;
        float dx=__fsub_rn(cx,X[3*p]), dy=__fsub_rn(cy,X[3*p+1]), dz=__fsub_rn(cz,X[3*p+2]);
        float d=__fadd_rn(__fadd_rn(__fmul_rn(dx,dx),__fmul_rn(dy,dy)),__fmul_rn(dz,dz));
        bool in = d < 0.64f;
        unsigned m=__ballot_sync(0xffffffffu,in);
        if (m){
            int pos=found+__popc(m & ((1u<<lane)-1u));
            if (in && pos<NS) list[pos]=p;
            found+=__popc(m);
            if (found>=NS) break;
        }
    }
    __syncwarp();
    int total = found<NS ? found : NS;
    int pad   = (found>0) ? list[0] : 0;
    g_nn[gw*NS+lane] = (lane<total) ? list[lane] : pad;
    if (lane==0){
        g_cnt[gw] = (found>0) ? 1 : 0;
        __threadfence();
        *(volatile int*)&g_ready[gw] = 1;
    }
}

// =============== 3) fused gather + MLP + maxpool (progressive) ===============
__global__ __launch_bounds__(256) void mlp_kernel(
    const float* __restrict__ xyz, const float* __restrict__ feat,
    const float* __restrict__ centers,
    const float* __restrict__ W1, const float* __restrict__ g1, const float* __restrict__ b1,
    const float* __restrict__ W2, const float* __restrict__ g2, const float* __restrict__ b2,
    const float* __restrict__ W3, const float* __restrict__ g3, const float* __restrict__ b3)
{
    __shared__ __align__(16) float h0[67*32];
    __shared__ __align__(16) float h1[64*32];
    __shared__ __align__(16) float h2[128*32];
    __shared__ int snn[NS];
    const float invs = 1.0f / sqrtf(1.0f + 1e-5f);

    int blk=blockIdx.x, b=blk/NP, c=blk%NP, tid=threadIdx.x;
    if (tid==0){
        volatile int* r=&g_ready[blk];
        while (!*r) __nanosleep(128);
        __threadfence();
    }
    __syncthreads();

    const float* X = xyz + (size_t)b*NN_*3;
    if (tid<NS) snn[tid]=g_nn[blk*NS+tid];
    __syncthreads();
    if (tid<NS){
        int p=snn[tid];
        h0[0*32+tid]=X[3*p]  -centers[blk*3];
        h0[1*32+tid]=X[3*p+1]-centers[blk*3+1];
        h0[2*32+tid]=X[3*p+2]-centers[blk*3+2];
    }
    for (int e=tid; e<CIN*32; e+=256){
        int ch=e>>5, s=e&31;
        h0[(3+ch)*32+s]=feat[((size_t)b*CIN+ch)*NN_+snn[s]];
    }
    __syncthreads();

    {
        int og=tid>>3, sg=tid&7, o0=og*2;
        float acc[2][4]={};
        const float4* hv=(const float4*)h0;
        for (int i=0;i<67;i++){
            float w0=W1[o0*67+i], w1=W1[(o0+1)*67+i];
            float4 a=hv[i*8+sg];
            acc[0][0]+=w0*a.x; acc[0][1]+=w0*a.y; acc[0][2]+=w0*a.z; acc[0][3]+=w0*a.w;
            acc[1][0]+=w1*a.x; acc[1][1]+=w1*a.y; acc[1][2]+=w1*a.z; acc[1][3]+=w1*a.w;
        }
        float4* ov=(float4*)h1;
#pragma unroll
        for (int k=0;k<2;k++){
            float sc=g1[o0+k]*invs, bb=b1[o0+k];
            ov[(o0+k)*8+sg]=make_float4(fmaxf(acc[k][0]*sc+bb,0.f),fmaxf(acc[k][1]*sc+bb,0.f),
                                        fmaxf(acc[k][2]*sc+bb,0.f),fmaxf(acc[k][3]*sc+bb,0.f));
        }
    }
    __syncthreads();

    {
        int og=tid>>2, sg=tid&3, o0=og*2;
        float acc[2][8]={};
        const float4* hv=(const float4*)h1;
        for (int i=0;i<64;i++){
            float w0=W2[o0*64+i], w1=W2[(o0+1)*64+i];
            float4 a0=hv[i*8+sg*2], a1=hv[i*8+sg*2+1];
            float av[8]={a0.x,a0.y,a0.z,a0.w,a1.x,a1.y,a1.z,a1.w};
#pragma unroll
            for (int s=0;s<8;s++){acc[0][s]+=w0*av[s]; acc[1][s]+=w1*av[s];}
        }
        float4* ov=(float4*)h2;
#pragma unroll
        for (int k=0;k<2;k++){
            float sc=g2[o0+k]*invs, bb=b2[o0+k];
            float r[8];
#pragma unroll
            for (int s=0;s<8;s++) r[s]=fmaxf(acc[k][s]*sc+bb,0.f);
            ov[(o0+k)*8+sg*2  ]=make_float4(r[0],r[1],r[2],r[3]);
            ov[(o0+k)*8+sg*2+1]=make_float4(r[4],r[5],r[6],r[7]);
        }
    }
    __syncthreads();

    {
        int og=tid>>2, sg=tid&3, o0=og*4;
        float acc[4][8]={};
        const float4* hv=(const float4*)h2;
        for (int i=0;i<128;i++){
            float4 a0=hv[i*8+sg*2], a1=hv[i*8+sg*2+1];
            float av[8]={a0.x,a0.y,a0.z,a0.w,a1.x,a1.y,a1.z,a1.w};
#pragma unroll
            for (int k=0;k<4;k++){
                float w=W3[(o0+k)*128+i];
#pragma unroll
                for (int s=0;s<8;s++) acc[k][s]+=w*av[s];
            }
        }
        int nonempty = g_cnt[blk];
#pragma unroll
        for (int k=0;k<4;k++){
            float sc=g3[o0+k]*invs, bb=b3[o0+k];
            float m=0.f;
#pragma unroll
            for (int s=0;s<8;s++) m=fmaxf(m, fmaxf(acc[k][s]*sc+bb,0.f));
            m=fmaxf(m,__shfl_xor_sync(0xffffffffu,m,1));
            m=fmaxf(m,__shfl_xor_sync(0xffffffffu,m,2));
            if (sg==0) g_x[((size_t)b*CD+o0+k)*NP+c] = nonempty ? m : 0.f;
        }
    }
}

// =============== 4a) q/k GEMM split-K partials ===============
__global__ __launch_bounds__(256) void qk_part(const float* __restrict__ Wq,
                                               const float* __restrict__ Wk)
{
    __shared__ float At[64][33], Bt[64][33];
    int bz=blockIdx.z;
    int which=bz&1, b=(bz>>1)&1, ks=bz>>2;
    const float* A = which ? Wk : Wq;
    const float* Xx = g_x + (size_t)b*CD*NP;
    float* P = g_part + (((size_t)(which*BB+b)*4+ks)*NP8*CD);
    int o0=blockIdx.y*64, c0=blockIdx.x*64;
    int tid=threadIdx.x, tx=tid&15, ty=tid>>4;
    float acc[4][4]={};
    int p0s=ks*512;
    for (int p0=p0s; p0<p0s+512; p0+=32){
#pragma unroll
        for (int tt=0;tt<8;tt++){
            int i=tid+tt*256, r=i>>5, kk=i&31;
            At[r][kk]=A[(size_t)(o0+r)*NP+p0+kk];
            Bt[r][kk]=Xx[(size_t)(c0+r)*NP+p0+kk];
        }
        __syncthreads();
#pragma unroll
        for (int kk=0;kk<32;kk++){
            float a[4],bv[4];
#pragma unroll
            for (int i=0;i<4;i++){ a[i]=At[ty*4+i][kk]; bv[i]=Bt[tx*4+i][kk]; }
#pragma unroll
            for (int i=0;i<4;i++)
#pragma unroll
                for (int j=0;j<4;j++) acc[i][j]+=a[i]*bv[j];
        }
        __syncthreads();
    }
#pragma unroll
    for (int i=0;i<4;i++)
#pragma unroll
        for (int j=0;j<4;j++)
            P[(size_t)(o0+ty*4+i)*CD + c0+tx*4+j]=acc[i][j];
}

__global__ __launch_bounds__(256) void qk_fin(const float* __restrict__ gq, const float* __restrict__ bq,
                                              const float* __restrict__ gk, const float* __restrict__ bk)
{
    const float invs = 1.0f / sqrtf(1.0f + 1e-5f);
    int i = blockIdx.x*256+threadIdx.x;
    int c = i & 255, o=(i>>8)&255, b=(i>>16)&1, which=i>>17;
    size_t base=(((size_t)(which*BB+b)*4)*NP8+o)*CD + c;
    float s = g_part[base] + g_part[base+(size_t)NP8*CD] + g_part[base+2*(size_t)NP8*CD] + g_part[base+3*(size_t)NP8*CD];
    const float* gg = which? gk:gq; const float* bb = which? bk:bq;
    float r = fmaxf(s*gg[o]*invs + bb[o], 0.f);
    (which? g_k : g_q)[((size_t)b*NP8+o)*CD+c]=r;
}

// =============== 4b) sim GEMM (TN) ===============
__global__ __launch_bounds__(256) void sim_gemm()
{
    __shared__ float Kt[16][64], Qt[16][64];
    int b=blockIdx.z;
    const float* K = g_k + (size_t)b*NP8*CD;
    const float* Q = g_q + (size_t)b*NP8*CD;
    float* S = g_sim + (size_t)b*CD*CD;
    int c0=blockIdx.y*64, d0=blockIdx.x*64;
    int tid=threadIdx.x, tx=tid&15, ty=tid>>4;
    float acc[4][4]={};
    for (int o0=0;o0<NP8;o0+=16){
#pragma unroll
        for (int t=0;t<4;t++){
            int i=tid+t*256, oo=i>>6, cc=i&63;
            Kt[oo][cc]=K[(size_t)(o0+oo)*CD+c0+cc];
            Qt[oo][cc]=Q[(size_t)(o0+oo)*CD+d0+cc];
        }
        __syncthreads();
#pragma unroll
        for (int oo=0;oo<16;oo++){
            float a[4],bv[4];
#pragma unroll
            for (int i=0;i<4;i++){ a[i]=Kt[oo][ty*4+i]; bv[i]=Qt[oo][tx*4+i]; }
#pragma unroll
            for (int i=0;i<4;i++)
#pragma unroll
                for (int j=0;j<4;j++) acc[i][j]+=a[i]*bv[j];
        }
        __syncthreads();
    }
#pragma unroll
    for (int i=0;i<4;i++)
#pragma unroll
        for (int j=0;j<4;j++)
            S[(size_t)(c0+ty*4+i)*CD + d0+tx*4+j]=acc[i][j];
}

// =============== 4c) squeeze ===============
__global__ __launch_bounds__(256) void squeeze_kernel()
{
    int gw=(blockIdx.x*256+threadIdx.x)>>5, lane=threadIdx.x&31;
    if (gw>=BB*CD) return;
    const float* row = g_x + (size_t)gw*NP;
    float m=-3.4e38f;
    for (int p=lane;p<NP;p+=32) m=fmaxf(m,row[p]);
#pragma unroll
    for (int off=16;off>0;off>>=1) m=fmaxf(m,__shfl_down_sync(0xffffffffu,m,off));
    if (lane==0) g_s[gw]=m;
}

// =============== 4d) excitation ===============
__global__ __launch_bounds__(256) void exc_kernel(const float* __restrict__ We1,
                                                  const float* __restrict__ We2)
{
    __shared__ float hid[32];
    int b=blockIdx.x, t=threadIdx.x;
    const float* s=g_s+b*CD;
    if (t<32){
        float a=0.f;
        for (int i=0;i<CD;i++) a+=We1[t*CD+i]*s[i];
        hid[t]=fmaxf(a,0.f);
    }
    __syncthreads();
    float a=0.f;
#pragma unroll
    for (int j=0;j<32;j++) a+=We2[t*32+j]*hid[j];
    g_e[b*CD+t]=1.f/(1.f+expf(-a));
}

// =============== 4e) softmax + fold alpha*e ===============
__global__ __launch_bounds__(256) void smax_kernel(const float* __restrict__ alpha)
{
    __shared__ float red[8];
    int row=blockIdx.x, b=row/CD, t=threadIdx.x;
    const float* S=g_sim+(size_t)row*CD;
    float* A=g_affE+(size_t)row*CD;
    float v=S[t];
    float m=v;
#pragma unroll
    for (int off=16;off>0;off>>=1) m=fmaxf(m,__shfl_xor_sync(0xffffffffu,m,off));
    if ((t&31)==0) red[t>>5]=m;
    __syncthreads();
    m=red[t&7];
#pragma unroll
    for (int off=4;off>0;off>>=1) m=fmaxf(m,__shfl_xor_sync(0xffffffffu,m,off));
    float tt=m-v;
    float m2=tt;
#pragma unroll
    for (int off=16;off>0;off>>=1) m2=fmaxf(m2,__shfl_xor_sync(0xffffffffu,m2,off));
    __syncthreads();
    if ((t&31)==0) red[t>>5]=m2;
    __syncthreads();
    m2=red[t&7];
#pragma unroll
    for (int off=4;off>0;off>>=1) m2=fmaxf(m2,__shfl_xor_sync(0xffffffffu,m2,off));
    float z=expf(tt-m2);
    float sum=z;
#pragma unroll
    for (int off=16;off>0;off>>=1) sum+=__shfl_xor_sync(0xffffffffu,sum,off);
    __syncthreads();
    if ((t&31)==0) red[t>>5]=sum;
    __syncthreads();
    sum=red[t&7];
#pragma unroll
    for (int off=4;off>0;off>>=1) sum+=__shfl_xor_sync(0xffffffffu,sum,off);
    A[t]=alpha[0]*(z/sum)*g_e[b*CD+t];
}

// =============== 4f) epilogue: out = affE @ x + x ===============
__global__ __launch_bounds__(256) void epi_gemm(float* __restrict__ out2)
{
    __shared__ float At[64][17], Bt[16][64];
    int b=blockIdx.z;
    const float* A=g_affE+(size_t)b*CD*CD;
    const float* X=g_x+(size_t)b*CD*NP;
    float* C=out2+(size_t)b*CD*NP;
    int c0=blockIdx.y*64, n0=blockIdx.x*64;
    int tid=threadIdx.x, tx=tid&15, ty=tid>>4;
    float acc[4][4]={};
    for (int d0=0;d0<CD;d0+=16){
#pragma unroll
        for (int t=0;t<4;t++){
            int i=tid+t*256, r=i>>4, kk=i&15;
            At[r][kk]=A[(size_t)(c0+r)*CD+d0+kk];
        }
#pragma unroll
        for (int t=0;t<4;t++){
            int i=tid+t*256, kk=i>>6, n=i&63;
            Bt[kk][n]=X[(size_t)(d0+kk)*NP+n0+n];
        }
        __syncthreads();
#pragma unroll
        for (int kk=0;kk<16;kk++){
            float a[4],bv[4];
#pragma unroll
            for (int i=0;i<4;i++){ a[i]=At[ty*4+i][kk]; bv[i]=Bt[kk][tx*4+i]; }
#pragma unroll
            for (int i=0;i<4;i++)
#pragma unroll
                for (int j=0;j<4;j++) acc[i][j]+=a[i]*bv[j];
        }
        __syncthreads();
    }
#pragma unroll
    for (int i=0;i<4;i++){
        int cc=c0+ty*4+i;
#pragma unroll
        for (int j=0;j<4;j++){
            int n=n0+tx*4+j;
            C[(size_t)cc*NP+n]=acc[i][j]+X[(size_t)cc*NP+n];
        }
    }
}

extern "C" void kernel_launch(void* const* d_in, const int* in_sizes, int n_in,
                              void* d_out, int out_size)
{
    const float* xyz  = (const float*)d_in[0];
    const float* feat = (const float*)d_in[1];
    const float* W1=(const float*)d_in[2],  *g1=(const float*)d_in[3],  *b1=(const float*)d_in[4];
    const float* W2=(const float*)d_in[5],  *g2=(const float*)d_in[6],  *b2=(const float*)d_in[7];
    const float* W3=(const float*)d_in[8],  *g3=(const float*)d_in[9],  *b3=(const float*)d_in[10];
    const float* Wq=(const float*)d_in[11], *gq=(const float*)d_in[12], *bq=(const float*)d_in[13];
    const float* Wk=(const float*)d_in[14], *gk=(const float*)d_in[15], *bk=(const float*)d_in[16];
    const float* We1=(const float*)d_in[17], *We2=(const float*)d_in[18];
    const float* alpha=(const float*)d_in[19];
    float* out = (float*)d_out;
    float* out2 = out + BB*NP*3;

    static cudaStream_t s_fps=nullptr, s_bq=nullptr, s_mlp=nullptr;
    static cudaEvent_t evInit=nullptr, evFPS=nullptr, evBQ=nullptr, evMLP=nullptr;
    if (!s_fps){
        cudaStreamCreateWithFlags(&s_fps, cudaStreamNonBlocking);
        cudaStreamCreateWithFlags(&s_bq,  cudaStreamNonBlocking);
        cudaStreamCreateWithFlags(&s_mlp, cudaStreamNonBlocking);
        cudaEventCreateWithFlags(&evInit, cudaEventDisableTiming);
        cudaEventCreateWithFlags(&evFPS,  cudaEventDisableTiming);
        cudaEventCreateWithFlags(&evBQ,   cudaEventDisableTiming);
        cudaEventCreateWithFlags(&evMLP,  cudaEventDisableTiming);
    }

    // smem: sxy 32768 + szz 16384 + sid 8192 + hist 2048 + xslot 192 +
    //       wvs 128 + wls 128 + wsum 64 + bbox 24  ≈ 59936
    size_t fps_smem = 32768 + 16384 + 8192 + 2048 + 192 + 128 + 128 + 64 + 24;
    cudaFuncSetAttribute(fps_kernel, cudaFuncAttributeMaxDynamicSharedMemorySize, (int)fps_smem);

    init_kernel<<<1, 256>>>();
    cudaEventRecord(evInit, 0);
    cudaStreamWaitEvent(s_fps, evInit, 0);
    cudaStreamWaitEvent(s_bq,  evInit, 0);
    cudaStreamWaitEvent(s_mlp, evInit, 0);

    fps_kernel<<<BB*FPS_CL, 512, fps_smem, s_fps>>>(xyz, out);
    ballquery_kernel<<<(BB*NP)/4, 128, 0, s_bq>>>(xyz, out);
    mlp_kernel<<<BB*NP, 256, 0, s_mlp>>>(xyz, feat, out, W1,g1,b1, W2,g2,b2, W3,g3,b3);

    cudaEventRecord(evFPS, s_fps);
    cudaEventRecord(evBQ,  s_bq);
    cudaEventRecord(evMLP, s_mlp);
    cudaStreamWaitEvent(0, evFPS, 0);
    cudaStreamWaitEvent(0, evBQ,  0);
    cudaStreamWaitEvent(0, evMLP, 0);

    {
        dim3 g(CD/64, NP8/64, 16);
        qk_part<<<g, 256>>>(Wq, Wk);
        qk_fin<<<(2*BB*NP8*CD)/256, 256>>>(gq,bq, gk,bk);
    }
    {
        dim3 g(CD/64, CD/64, BB);
        sim_gemm<<<g, 256>>>();
    }
    squeeze_kernel<<<(BB*CD)/8, 256>>>();
    exc_kernel<<<BB, 256>>>(We1, We2);
    smax_kernel<<<BB*CD, 256>>>(alpha);
    {
        dim3 g(NP/64, CD/64, BB);
        epi_gemm<<<g, 256>>>(out2);
    }
}

// round 12
// speedup vs baseline: 1.1712x; 1.1712x over previous
#include <cuda_runtime.h>
#include <stdint.h>
#include <math.h>

#define BB   2
#define NN_  16384
#define NP   2048
#define NS   32
#define CIN  64
#define CD   256
#define NP8  256

// ---- scratch (device globals; allocation is forbidden) ----
__device__ int   g_nn[BB*NP*NS];
__device__ int   g_cnt[BB*NP];
__device__ float g_x   [BB*CD*NP];
__device__ float g_q   [BB*NP8*CD];
__device__ float g_k   [BB*NP8*CD];
__device__ float g_sim [BB*CD*CD];
__device__ float g_affE[BB*CD*CD];
__device__ float g_s   [BB*CD];
__device__ float g_e   [BB*CD];
__device__ float g_part[2*BB*4*NP8*CD];
__device__ int   g_prog[BB];
__device__ int   g_ready[BB*NP];
__device__ int   g_mlpdone[BB*4*32];   // per-(batch,chunk) counter, 128B padded

__device__ __forceinline__ unsigned f2ord(float f){
    unsigned u=__float_as_uint(f);
    return (u&0x80000000u)? ~u : (u|0x80000000u);
}
__device__ __forceinline__ float ord2f(unsigned v){
    unsigned u=(v&0x80000000u)? (v&0x7fffffffu) : ~v;
    return __uint_as_float(u);
}
__device__ __forceinline__ int spread3(int b){
    return (b&1) | ((b&2)<<2) | ((b&4)<<4);
}

// =============== 0) init: reset progress/ready flags ===============
__global__ void init_kernel()
{
    int t = blockIdx.x*blockDim.x + threadIdx.x;
    if (t < BB) g_prog[t] = 0;
    if (t < BB*4*32) g_mlpdone[t] = 0;
    for (int i = t; i < BB*NP; i += gridDim.x*blockDim.x) g_ready[i] = 0;
}

// =====================================================================
// 1) FPS (R8): 512 thr/CTA, 1 CTA/batch, 32 pts/thread as two 16-pt
//    groups, Morton sort, u64 keys, 1 barrier/iter, progress publishing.
// =====================================================================
__global__ __launch_bounds__(512) void fps_kernel(const float* __restrict__ xyz,
                                                  float* __restrict__ d_out)
{
    extern __shared__ char smraw[];
    float2* sxy = (float2*)smraw;
    float*  szz = (float*)(sxy + NN_);
    unsigned short* sid = (unsigned short*)(szz + NN_);
    int* hist = (int*)(sid + NN_);
    unsigned* wvs = (unsigned*)(hist + 512);
    unsigned* wls = wvs + 32;
    int* wsum = (int*)(wls + 32);
    unsigned* bmin = (unsigned*)(wsum + 16);
    unsigned* bmax = bmin + 3;

    const int b = blockIdx.x, t = threadIdx.x;
    const int lane = t & 31, w = t >> 5;
    const float* X = xyz + (size_t)b*NN_*3;

    if (t < 512) hist[t] = 0;
    if (t < 3) { bmin[t] = 0xFFFFFFFFu; bmax[t] = 0u; }
    __syncthreads();

    {
        float lx=3.4e38f, ly=3.4e38f, lz=3.4e38f, hx=-3.4e38f, hy=-3.4e38f, hz=-3.4e38f;
#pragma unroll
        for (int j=0;j<32;j++){
            int p=j*512+t;
            float x=X[3*p], y=X[3*p+1], z=X[3*p+2];
            lx=fminf(lx,x); hx=fmaxf(hx,x);
            ly=fminf(ly,y); hy=fmaxf(hy,y);
            lz=fminf(lz,z); hz=fmaxf(hz,z);
        }
        atomicMin(&bmin[0], f2ord(lx)); atomicMax(&bmax[0], f2ord(hx));
        atomicMin(&bmin[1], f2ord(ly)); atomicMax(&bmax[1], f2ord(hy));
        atomicMin(&bmin[2], f2ord(lz)); atomicMax(&bmax[2], f2ord(hz));
    }
    __syncthreads();
    float LX=ord2f(bmin[0]), LY=ord2f(bmin[1]), LZ=ord2f(bmin[2]);
    float invx=8.f/fmaxf(ord2f(bmax[0])-LX,1e-12f);
    float invy=8.f/fmaxf(ord2f(bmax[1])-LY,1e-12f);
    float invz=8.f/fmaxf(ord2f(bmax[2])-LZ,1e-12f);

#pragma unroll
    for (int j=0;j<32;j++){
        int p=j*512+t;
        float x=X[3*p], y=X[3*p+1], z=X[3*p+2];
        int bx=min(7,(int)((x-LX)*invx));
        int by=min(7,(int)((y-LY)*invy));
        int bz=min(7,(int)((z-LZ)*invz));
        atomicAdd(&hist[(spread3(bx)<<2)|(spread3(by)<<1)|spread3(bz)],1);
    }
    __syncthreads();

    int cnt=hist[t], v=cnt;
#pragma unroll
    for (int d=1; d<32; d<<=1){ int o=__shfl_up_sync(0xffffffffu, v, d); if (lane>=d) v+=o; }
    if (lane==31) wsum[w]=v;
    __syncthreads();
    if (t<16){
        int s=wsum[t];
#pragma unroll
        for (int d=1; d<16; d<<=1){ int o=__shfl_up_sync(0x0000ffffu, s, d); if (t>=d) s+=o; }
        wsum[t]=s;
    }
    __syncthreads();
    { int add=(w>0)? wsum[w-1]:0; hist[t]=v+add-cnt; }
    __syncthreads();

#pragma unroll
    for (int j=0;j<32;j++){
        int p=j*512+t;
        float x=X[3*p], y=X[3*p+1], z=X[3*p+2];
        int bx=min(7,(int)((x-LX)*invx));
        int by=min(7,(int)((y-LY)*invy));
        int bz=min(7,(int)((z-LZ)*invz));
        int pos=atomicAdd(&hist[(spread3(bx)<<2)|(spread3(by)<<1)|spread3(bz)],1);
        int A=((pos&31)<<9)|(pos>>5);
        sxy[A]=make_float2(x,y); szz[A]=z; sid[A]=(unsigned short)p;
    }
    __syncthreads();

    float mind[32];
    float glx[2],gly[2],glz[2],ghx[2],ghy[2],ghz[2];
#pragma unroll
    for (int g=0; g<2; g++){
        float lx=3.4e38f, ly=3.4e38f, lz=3.4e38f, hx=-3.4e38f, hy=-3.4e38f, hz=-3.4e38f;
#pragma unroll
        for (int j=g*16; j<g*16+16; j++){
            int A=(j<<9)|t;
            float2 xy=sxy[A]; float zz=szz[A];
            lx=fminf(lx,xy.x); hx=fmaxf(hx,xy.x);
            ly=fminf(ly,xy.y); hy=fmaxf(hy,xy.y);
            lz=fminf(lz,zz);   hz=fmaxf(hz,zz);
            mind[j]=3.4e38f;
        }
        glx[g]=lx; gly[g]=ly; glz[g]=lz; ghx[g]=hx; ghy[g]=hy; ghz[g]=hz;
    }
    float wlx=fminf(glx[0],glx[1]), wly=fminf(gly[0],gly[1]), wlz=fminf(glz[0],glz[1]);
    float whx=fmaxf(ghx[0],ghx[1]), why_=fmaxf(ghy[0],ghy[1]), whz=fmaxf(ghz[0],ghz[1]);
#pragma unroll
    for (int off=16; off>0; off>>=1){
        wlx=fminf(wlx,__shfl_xor_sync(0xffffffffu,wlx,off));
        wly=fminf(wly,__shfl_xor_sync(0xffffffffu,wly,off));
        wlz=fminf(wlz,__shfl_xor_sync(0xffffffffu,wlz,off));
        whx=fmaxf(whx,__shfl_xor_sync(0xffffffffu,whx,off));
        why_=fmaxf(why_,__shfl_xor_sync(0xffffffffu,why_,off));
        whz=fmaxf(whz,__shfl_xor_sync(0xffffffffu,whz,off));
    }

    unsigned long long gkey[2]={0ull,0ull};
    float gval[2]={3.4e38f,3.4e38f};
    unsigned wmx=0u, wlo=0u; float wval=3.4e38f;

    float nx=X[0], ny=X[1], nz=X[2];
    if (t==0){
        d_out[(size_t)b*NP*3]=nx; d_out[(size_t)b*NP*3+1]=ny; d_out[(size_t)b*NP*3+2]=nz;
    }

    for (int it=1; it<NP; it++){
        int buf=(it&1)*16;
        float wdx=fmaxf(fmaxf(wlx-nx, nx-whx),0.f);
        float wdy=fmaxf(fmaxf(wly-ny, ny-why_),0.f);
        float wdz=fmaxf(fmaxf(wlz-nz, nz-whz),0.f);
        float wdd=wdx*wdx+wdy*wdy+wdz*wdz;
        if (wdd*0.99f < wval){
#pragma unroll
            for (int g=0; g<2; g++){
                float ddx=fmaxf(fmaxf(glx[g]-nx, nx-ghx[g]),0.f);
                float ddy=fmaxf(fmaxf(gly[g]-ny, ny-ghy[g]),0.f);
                float ddz=fmaxf(fmaxf(glz[g]-nz, nz-ghz[g]),0.f);
                float dd=ddx*ddx+ddy*ddy+ddz*ddz;
                if (dd*0.99f < gval[g]){
                    unsigned long long bk=0ull;
#pragma unroll
                    for (int j=g*16; j<g*16+16; j++){
                        int A=(j<<9)|t;
                        float2 xy=sxy[A]; float zz=szz[A];
                        float dx=__fsub_rn(xy.x,nx), dy=__fsub_rn(xy.y,ny), dz=__fsub_rn(zz,nz);
                        float d=__fadd_rn(__fadd_rn(__fmul_rn(dx,dx),__fmul_rn(dy,dy)),__fmul_rn(dz,dz));
                        float m=fminf(mind[j],d); mind[j]=m;
                        unsigned long long key=((unsigned long long)__float_as_uint(m)<<32)
                            | (unsigned)((((unsigned)sid[A])^0xFFFFu)<<16) | (unsigned)A;
                        bk = (bk>key)? bk : key;
                    }
                    gkey[g]=bk; gval[g]=__uint_as_float((unsigned)(bk>>32));
                }
            }
            unsigned long long tk = (gkey[0]>gkey[1])? gkey[0]:gkey[1];
            unsigned uv=(unsigned)(tk>>32);
            unsigned mx=__reduce_max_sync(0xffffffffu, uv);
            unsigned lo=(uv==mx)? (unsigned)tk : 0u;
            unsigned mlo=__reduce_max_sync(0xffffffffu, lo);
            wmx=mx; wlo=mlo; wval=__uint_as_float(mx);
        }
        if (lane==0){ wvs[buf+w]=wmx; wls[buf+w]=wlo; }
        __syncthreads();
        unsigned uv2=wvs[buf+(lane&15)], lo2=wls[buf+(lane&15)];
        unsigned m2=__reduce_max_sync(0xffffffffu, uv2);
        unsigned c2=(uv2==m2)? lo2 : 0u;
        unsigned l2=__reduce_max_sync(0xffffffffu, c2);
        int wA=(int)(l2 & 0xFFFFu);
        float2 cc=sxy[wA];
        nx=cc.x; ny=cc.y; nz=szz[wA];
        if (t==0){
            d_out[((size_t)b*NP+it)*3  ]=nx;
            d_out[((size_t)b*NP+it)*3+1]=ny;
            d_out[((size_t)b*NP+it)*3+2]=nz;
            if ((it&7)==7 || it==NP-1){
                __threadfence();
                *(volatile int*)&g_prog[b] = it+1;
            }
        }
    }
}

// =============== 2) ball query (warp per center, progressive) ===============
__global__ __launch_bounds__(128) void ballquery_kernel(const float* __restrict__ xyz,
                                                        const float* __restrict__ centers)
{
    int gw = (blockIdx.x*blockDim.x + threadIdx.x)>>5;
    int lane = threadIdx.x & 31;
    if (gw >= BB*NP) return;
    int b = gw / NP, c = gw % NP;
    {
        volatile int* pr = &g_prog[b];
        while (*pr <= c) __nanosleep(128);
        __threadfence();
    }
    const float* X = xyz + (size_t)b*NN_*3;
    float cx=centers[gw*3], cy=centers[gw*3+1], cz=centers[gw*3+2];
    __shared__ int lists[4][NS];
    int* list = lists[threadIdx.x>>5];
    int found=0;
    for (int base=0; base<NN_; base+=32){
        int p=base+lane;
        float dx=__fsub_rn(cx,X[3*p]), dy=__fsub_rn(cy,X[3*p+1]), dz=__fsub_rn(cz,X[3*p+2]);
        float d=__fadd_rn(__fadd_rn(__fmul_rn(dx,dx),__fmul_rn(dy,dy)),__fmul_rn(dz,dz));
        bool in = d < 0.64f;
        unsigned m=__ballot_sync(0xffffffffu,in);
        if (m){
            int pos=found+__popc(m & ((1u<<lane)-1u));
            if (in && pos<NS) list[pos]=p;
            found+=__popc(m);
            if (found>=NS) break;
        }
    }
    __syncwarp();
    int total = found<NS ? found : NS;
    int pad   = (found>0) ? list[0] : 0;
    g_nn[gw*NS+lane] = (lane<total) ? list[lane] : pad;
    if (lane==0){
        g_cnt[gw] = (found>0) ? 1 : 0;
        __threadfence();
        *(volatile int*)&g_ready[gw] = 1;
    }
}

// =============== 3) fused gather + MLP + maxpool (progressive) ===============
__global__ __launch_bounds__(256) void mlp_kernel(
    const float* __restrict__ xyz, const float* __restrict__ feat,
    const float* __restrict__ centers,
    const float* __restrict__ W1, const float* __restrict__ g1, const float* __restrict__ b1,
    const float* __restrict__ W2, const float* __restrict__ g2, const float* __restrict__ b2,
    const float* __restrict__ W3, const float* __restrict__ g3, const float* __restrict__ b3)
{
    __shared__ __align__(16) float h0[67*32];
    __shared__ __align__(16) float h1[64*32];
    __shared__ __align__(16) float h2[128*32];
    __shared__ int snn[NS];
    const float invs = 1.0f / sqrtf(1.0f + 1e-5f);

    int blk=blockIdx.x, b=blk/NP, c=blk%NP, tid=threadIdx.x;
    if (tid==0){
        volatile int* r=&g_ready[blk];
        while (!*r) __nanosleep(128);
        __threadfence();
    }
    __syncthreads();

    const float* X = xyz + (size_t)b*NN_*3;
    if (tid<NS) snn[tid]=g_nn[blk*NS+tid];
    __syncthreads();
    if (tid<NS){
        int p=snn[tid];
        h0[0*32+tid]=X[3*p]  -centers[blk*3];
        h0[1*32+tid]=X[3*p+1]-centers[blk*3+1];
        h0[2*32+tid]=X[3*p+2]-centers[blk*3+2];
    }
    for (int e=tid; e<CIN*32; e+=256){
        int ch=e>>5, s=e&31;
        h0[(3+ch)*32+s]=feat[((size_t)b*CIN+ch)*NN_+snn[s]];
    }
    __syncthreads();

    {
        int og=tid>>3, sg=tid&7, o0=og*2;
        float acc[2][4]={};
        const float4* hv=(const float4*)h0;
        for (int i=0;i<67;i++){
            float w0=W1[o0*67+i], w1=W1[(o0+1)*67+i];
            float4 a=hv[i*8+sg];
            acc[0][0]+=w0*a.x; acc[0][1]+=w0*a.y; acc[0][2]+=w0*a.z; acc[0][3]+=w0*a.w;
            acc[1][0]+=w1*a.x; acc[1][1]+=w1*a.y; acc[1][2]+=w1*a.z; acc[1][3]+=w1*a.w;
        }
        float4* ov=(float4*)h1;
#pragma unroll
        for (int k=0;k<2;k++){
            float sc=g1[o0+k]*invs, bb=b1[o0+k];
            ov[(o0+k)*8+sg]=make_float4(fmaxf(acc[k][0]*sc+bb,0.f),fmaxf(acc[k][1]*sc+bb,0.f),
                                        fmaxf(acc[k][2]*sc+bb,0.f),fmaxf(acc[k][3]*sc+bb,0.f));
        }
    }
    __syncthreads();

    {
        int og=tid>>2, sg=tid&3, o0=og*2;
        float acc[2][8]={};
        const float4* hv=(const float4*)h1;
        for (int i=0;i<64;i++){
            float w0=W2[o0*64+i], w1=W2[(o0+1)*64+i];
            float4 a0=hv[i*8+sg*2], a1=hv[i*8+sg*2+1];
            float av[8]={a0.x,a0.y,a0.z,a0.w,a1.x,a1.y,a1.z,a1.w};
#pragma unroll
            for (int s=0;s<8;s++){acc[0][s]+=w0*av[s]; acc[1][s]+=w1*av[s];}
        }
        float4* ov=(float4*)h2;
#pragma unroll
        for (int k=0;k<2;k++){
            float sc=g2[o0+k]*invs, bb=b2[o0+k];
            float r[8];
#pragma unroll
            for (int s=0;s<8;s++) r[s]=fmaxf(acc[k][s]*sc+bb,0.f);
            ov[(o0+k)*8+sg*2  ]=make_float4(r[0],r[1],r[2],r[3]);
            ov[(o0+k)*8+sg*2+1]=make_float4(r[4],r[5],r[6],r[7]);
        }
    }
    __syncthreads();

    {
        int og=tid>>2, sg=tid&3, o0=og*4;
        float acc[4][8]={};
        const float4* hv=(const float4*)h2;
        for (int i=0;i<128;i++){
            float4 a0=hv[i*8+sg*2], a1=hv[i*8+sg*2+1];
            float av[8]={a0.x,a0.y,a0.z,a0.w,a1.x,a1.y,a1.z,a1.w};
#pragma unroll
            for (int k=0;k<4;k++){
                float w=W3[(o0+k)*128+i];
#pragma unroll
                for (int s=0;s<8;s++) acc[k][s]+=w*av[s];
            }
        }
        int nonempty = g_cnt[blk];
#pragma unroll
        for (int k=0;k<4;k++){
            float sc=g3[o0+k]*invs, bb=b3[o0+k];
            float m=0.f;
#pragma unroll
            for (int s=0;s<8;s++) m=fmaxf(m, fmaxf(acc[k][s]*sc+bb,0.f));
            m=fmaxf(m,__shfl_xor_sync(0xffffffffu,m,1));
            m=fmaxf(m,__shfl_xor_sync(0xffffffffu,m,2));
            if (sg==0) g_x[((size_t)b*CD+o0+k)*NP+c] = nonempty ? m : 0.f;
        }
    }
    __syncthreads();
    if (tid==0){
        __threadfence();
        atomicAdd(&g_mlpdone[(b*4 + (c>>9))*32], 1);
    }
}

// =============== 4a) q/k GEMM split-K partials (chunk-progressive) ===============
__global__ __launch_bounds__(256) void qk_part(const float* __restrict__ Wq,
                                               const float* __restrict__ Wk)
{
    __shared__ float At[64][33], Bt[64][33];
    int bz=blockIdx.z;
    int which=bz&1, b=(bz>>1)&1, ks=bz>>2;
    int tid=threadIdx.x;
    if (tid==0){
        volatile int* ctr=&g_mlpdone[(b*4+ks)*32];
        while (*ctr < 512) __nanosleep(256);
        __threadfence();
    }
    __syncthreads();

    const float* A = which ? Wk : Wq;
    const float* Xx = g_x + (size_t)b*CD*NP;
    float* P = g_part + (((size_t)(which*BB+b)*4+ks)*NP8*CD);
    int o0=blockIdx.y*64, c0=blockIdx.x*64;
    int tx=tid&15, ty=tid>>4;
    float acc[4][4]={};
    int p0s=ks*512;
    for (int p0=p0s; p0<p0s+512; p0+=32){
#pragma unroll
        for (int tt=0;tt<8;tt++){
            int i=tid+tt*256, r=i>>5, kk=i&31;
            At[r][kk]=A[(size_t)(o0+r)*NP+p0+kk];
            Bt[r][kk]=Xx[(size_t)(c0+r)*NP+p0+kk];
        }
        __syncthreads();
#pragma unroll
        for (int kk=0;kk<32;kk++){
            float a[4],bv[4];
#pragma unroll
            for (int i=0;i<4;i++){ a[i]=At[ty*4+i][kk]; bv[i]=Bt[tx*4+i][kk]; }
#pragma unroll
            for (int i=0;i<4;i++)
#pragma unroll
                for (int j=0;j<4;j++) acc[i][j]+=a[i]*bv[j];
        }
        __syncthreads();
    }
#pragma unroll
    for (int i=0;i<4;i++)
#pragma unroll
        for (int j=0;j<4;j++)
            P[(size_t)(o0+ty*4+i)*CD + c0+tx*4+j]=acc[i][j];
}

__global__ __launch_bounds__(256) void qk_fin(const float* __restrict__ gq, const float* __restrict__ bq,
                                              const float* __restrict__ gk, const float* __restrict__ bk)
{
    const float invs = 1.0f / sqrtf(1.0f + 1e-5f);
    int i = blockIdx.x*256+threadIdx.x;
    int c = i & 255, o=(i>>8)&255, b=(i>>16)&1, which=i>>17;
    size_t base=(((size_t)(which*BB+b)*4)*NP8+o)*CD + c;
    float s = g_part[base] + g_part[base+(size_t)NP8*CD] + g_part[base+2*(size_t)NP8*CD] + g_part[base+3*(size_t)NP8*CD];
    const float* gg = which? gk:gq; const float* bb = which? bk:bq;
    float r = fmaxf(s*gg[o]*invs + bb[o], 0.f);
    (which? g_k : g_q)[((size_t)b*NP8+o)*CD+c]=r;
}

// =============== 4b) sim GEMM (TN) ===============
__global__ __launch_bounds__(256) void sim_gemm()
{
    __shared__ float Kt[16][64], Qt[16][64];
    int b=blockIdx.z;
    const float* K = g_k + (size_t)b*NP8*CD;
    const float* Q = g_q + (size_t)b*NP8*CD;
    float* S = g_sim + (size_t)b*CD*CD;
    int c0=blockIdx.y*64, d0=blockIdx.x*64;
    int tid=threadIdx.x, tx=tid&15, ty=tid>>4;
    float acc[4][4]={};
    for (int o0=0;o0<NP8;o0+=16){
#pragma unroll
        for (int t=0;t<4;t++){
            int i=tid+t*256, oo=i>>6, cc=i&63;
            Kt[oo][cc]=K[(size_t)(o0+oo)*CD+c0+cc];
            Qt[oo][cc]=Q[(size_t)(o0+oo)*CD+d0+cc];
        }
        __syncthreads();
#pragma unroll
        for (int oo=0;oo<16;oo++){
            float a[4],bv[4];
#pragma unroll
            for (int i=0;i<4;i++){ a[i]=Kt[oo][ty*4+i]; bv[i]=Qt[oo][tx*4+i]; }
#pragma unroll
            for (int i=0;i<4;i++)
#pragma unroll
                for (int j=0;j<4;j++) acc[i][j]+=a[i]*bv[j];
        }
        __syncthreads();
    }
#pragma unroll
    for (int i=0;i<4;i++)
#pragma unroll
        for (int j=0;j<4;j++)
            S[(size_t)(c0+ty*4+i)*CD + d0+tx*4+j]=acc[i][j];
}

// =============== 4c) squeeze ===============
__global__ __launch_bounds__(256) void squeeze_kernel()
{
    int gw=(blockIdx.x*256+threadIdx.x)>>5, lane=threadIdx.x&31;
    if (gw>=BB*CD) return;
    const float* row = g_x + (size_t)gw*NP;
    float m=-3.4e38f;
    for (int p=lane;p<NP;p+=32) m=fmaxf(m,row[p]);
#pragma unroll
    for (int off=16;off>0;off>>=1) m=fmaxf(m,__shfl_down_sync(0xffffffffu,m,off));
    if (lane==0) g_s[gw]=m;
}

// =============== 4d) excitation ===============
__global__ __launch_bounds__(256) void exc_kernel(const float* __restrict__ We1,
                                                  const float* __restrict__ We2)
{
    __shared__ float hid[32];
    int b=blockIdx.x, t=threadIdx.x;
    const float* s=g_s+b*CD;
    if (t<32){
        float a=0.f;
        for (int i=0;i<CD;i++) a+=We1[t*CD+i]*s[i];
        hid[t]=fmaxf(a,0.f);
    }
    __syncthreads();
    float a=0.f;
#pragma unroll
    for (int j=0;j<32;j++) a+=We2[t*32+j]*hid[j];
    g_e[b*CD+t]=1.f/(1.f+expf(-a));
}

// =============== 4e) softmax + fold alpha*e ===============
__global__ __launch_bounds__(256) void smax_kernel(const float* __restrict__ alpha)
{
    __shared__ float red[8];
    int row=blockIdx.x, b=row/CD, t=threadIdx.x;
    const float* S=g_sim+(size_t)row*CD;
    float* A=g_affE+(size_t)row*CD;
    float v=S[t];
    float m=v;
#pragma unroll
    for (int off=16;off>0;off>>=1) m=fmaxf(m,__shfl_xor_sync(0xffffffffu,m,off));
    if ((t&31)==0) red[t>>5]=m;
    __syncthreads();
    m=red[t&7];
#pragma unroll
    for (int off=4;off>0;off>>=1) m=fmaxf(m,__shfl_xor_sync(0xffffffffu,m,off));
    float tt=m-v;
    float m2=tt;
#pragma unroll
    for (int off=16;off>0;off>>=1) m2=fmaxf(m2,__shfl_xor_sync(0xffffffffu,m2,off));
    __syncthreads();
    if ((t&31)==0) red[t>>5]=m2;
    __syncthreads();
    m2=red[t&7];
#pragma unroll
    for (int off=4;off>0;off>>=1) m2=fmaxf(m2,__shfl_xor_sync(0xffffffffu,m2,off));
    float z=expf(tt-m2);
    float sum=z;
#pragma unroll
    for (int off=16;off>0;off>>=1) sum+=__shfl_xor_sync(0xffffffffu,sum,off);
    __syncthreads();
    if ((t&31)==0) red[t>>5]=sum;
    __syncthreads();
    sum=red[t&7];
#pragma unroll
    for (int off=4;off>0;off>>=1) sum+=__shfl_xor_sync(0xffffffffu,sum,off);
    A[t]=alpha[0]*(z/sum)*g_e[b*CD+t];
}

// =============== 4f) epilogue: out = affE @ x + x ===============
__global__ __launch_bounds__(256) void epi_gemm(float* __restrict__ out2)
{
    __shared__ float At[64][17], Bt[16][64];
    int b=blockIdx.z;
    const float* A=g_affE+(size_t)b*CD*CD;
    const float* X=g_x+(size_t)b*CD*NP;
    float* C=out2+(size_t)b*CD*NP;
    int c0=blockIdx.y*64, n0=blockIdx.x*64;
    int tid=threadIdx.x, tx=tid&15, ty=tid>>4;
    float acc[4][4]={};
    for (int d0=0;d0<CD;d0+=16){
#pragma unroll
        for (int t=0;t<4;t++){
            int i=tid+t*256, r=i>>4, kk=i&15;
            At[r][kk]=A[(size_t)(c0+r)*CD+d0+kk];
        }
#pragma unroll
        for (int t=0;t<4;t++){
            int i=tid+t*256, kk=i>>6, n=i&63;
            Bt[kk][n]=X[(size_t)(d0+kk)*NP+n0+n];
        }
        __syncthreads();
#pragma unroll
        for (int kk=0;kk<16;kk++){
            float a[4],bv[4];
#pragma unroll
            for (int i=0;i<4;i++){ a[i]=At[ty*4+i][kk]; bv[i]=Bt[kk][tx*4+i]; }
#pragma unroll
            for (int i=0;i<4;i++)
#pragma unroll
                for (int j=0;j<4;j++) acc[i][j]+=a[i]*bv[j];
        }
        __syncthreads();
    }
#pragma unroll
    for (int i=0;i<4;i++){
        int cc=c0+ty*4+i;
#pragma unroll
        for (int j=0;j<4;j++){
            int n=n0+tx*4+j;
            C[(size_t)cc*NP+n]=acc[i][j]+X[(size_t)cc*NP+n];
        }
    }
}

extern "C" void kernel_launch(void* const* d_in, const int* in_sizes, int n_in,
                              void* d_out, int out_size)
{
    const float* xyz  = (const float*)d_in[0];
    const float* feat = (const float*)d_in[1];
    const float* W1=(const float*)d_in[2],  *g1=(const float*)d_in[3],  *b1=(const float*)d_in[4];
    const float* W2=(const float*)d_in[5],  *g2=(const float*)d_in[6],  *b2=(const float*)d_in[7];
    const float* W3=(const float*)d_in[8],  *g3=(const float*)d_in[9],  *b3=(const float*)d_in[10];
    const float* Wq=(const float*)d_in[11], *gq=(const float*)d_in[12], *bq=(const float*)d_in[13];
    const float* Wk=(const float*)d_in[14], *gk=(const float*)d_in[15], *bk=(const float*)d_in[16];
    const float* We1=(const float*)d_in[17], *We2=(const float*)d_in[18];
    const float* alpha=(const float*)d_in[19];
    float* out = (float*)d_out;
    float* out2 = out + BB*NP*3;

    // EXACTLY R8's stream/event topology (3 streams, 4 events) — known to
    // pass the harness's graph-teardown memory check.
    static cudaStream_t s_fps=nullptr, s_bq=nullptr, s_mlp=nullptr;
    static cudaEvent_t evInit=nullptr, evFPS=nullptr, evBQ=nullptr, evMLP=nullptr;
    if (!s_fps){
        cudaStreamCreateWithFlags(&s_fps, cudaStreamNonBlocking);
        cudaStreamCreateWithFlags(&s_bq,  cudaStreamNonBlocking);
        cudaStreamCreateWithFlags(&s_mlp, cudaStreamNonBlocking);
        cudaEventCreateWithFlags(&evInit, cudaEventDisableTiming);
        cudaEventCreateWithFlags(&evFPS,  cudaEventDisableTiming);
        cudaEventCreateWithFlags(&evBQ,   cudaEventDisableTiming);
        cudaEventCreateWithFlags(&evMLP,  cudaEventDisableTiming);
    }

    size_t fps_smem = 131072 + 65536 + 32768 + 2048 + 256 + 64 + 24;
    cudaFuncSetAttribute(fps_kernel, cudaFuncAttributeMaxDynamicSharedMemorySize, (int)fps_smem);

    init_kernel<<<1, 256>>>();
    cudaEventRecord(evInit, 0);
    cudaStreamWaitEvent(s_fps, evInit, 0);
    cudaStreamWaitEvent(s_bq,  evInit, 0);
    cudaStreamWaitEvent(s_mlp, evInit, 0);

    fps_kernel<<<BB, 512, fps_smem, s_fps>>>(xyz, out);
    ballquery_kernel<<<(BB*NP)/4, 128, 0, s_bq>>>(xyz, out);
    mlp_kernel<<<BB*NP, 256, 0, s_mlp>>>(xyz, feat, out, W1,g1,b1, W2,g2,b2, W3,g3,b3);
    {
        // chunk-progressive qk_part rides s_bq after ballquery (no new stream)
        dim3 g(CD/64, NP8/64, 16);
        qk_part<<<g, 256, 0, s_bq>>>(Wq, Wk);
    }

    cudaEventRecord(evFPS, s_fps);
    cudaEventRecord(evBQ,  s_bq);     // covers ballquery + qk_part
    cudaEventRecord(evMLP, s_mlp);
    cudaStreamWaitEvent(0, evFPS, 0);
    cudaStreamWaitEvent(0, evBQ,  0);
    cudaStreamWaitEvent(0, evMLP, 0);

    // tail on default stream
    qk_fin<<<(2*BB*NP8*CD)/256, 256>>>(gq,bq, gk,bk);
    {
        dim3 g(CD/64, CD/64, BB);
        sim_gemm<<<g, 256>>>();
    }
    squeeze_kernel<<<(BB*CD)/8, 256>>>();
    exc_kernel<<<BB, 256>>>(We1, We2);
    smax_kernel<<<BB*CD, 256>>>(alpha);
    {
        dim3 g(NP/64, CD/64, BB);
        epi_gemm<<<g, 256>>>(out2);
    }
}